// round 11
// baseline (speedup 1.0000x reference)
#include <cuda_runtime.h>
#include <math.h>

#define N_NODES 100000
#define N_EDGES 1600000
#define HIDDEN  128
#define N_GRAPHS 64
#define ETILE   8

// ---------------- device scratch (static allocs only) ----------------
__device__ float g_h   [N_NODES * HIDDEN];
__device__ float g_P   [N_NODES * 512];
__device__ float g_agg1[N_NODES * 3];
__device__ float g_Wcat[128 * 512];
__device__ float g_pool[N_GRAPHS * HIDDEN];
__device__ float g_cnt [N_GRAPHS];
// sort scratch
__device__ int g_cntN [N_NODES];
__device__ int g_off2 [N_NODES];
__device__ int g_esrc [N_EDGES];
__device__ int g_edst [N_EDGES];
__device__ int g_eperm[N_EDGES];

__device__ __forceinline__ float sigmoidf_(float x) { return 1.f / (1.f + expf(-x)); }
__device__ __forceinline__ float softplusf_(float x) {
    return fmaxf(x, 0.f) + log1pf(expf(-fabsf(x)));
}

// ---------------- packed f32x2 helpers (FFMA2) ----------------
typedef unsigned long long ull;
__device__ __forceinline__ ull pk2(float lo, float hi) {
    ull r; asm("mov.b64 %0, {%1, %2};" : "=l"(r) : "f"(lo), "f"(hi)); return r;
}
__device__ __forceinline__ ull fma2(ull a, ull b, ull c) {
    ull d; asm("fma.rn.f32x2 %0, %1, %2, %3;" : "=l"(d) : "l"(a), "l"(b), "l"(c)); return d;
}
__device__ __forceinline__ float2 upk(ull v) {
    float2 r; asm("mov.b64 {%0, %1}, %2;" : "=f"(r.x), "=f"(r.y) : "l"(v)); return r;
}

// ---------------- sort: count-sort edges by dst ----------------
__global__ void k_zero_cnt() {
    int i = blockIdx.x * blockDim.x + threadIdx.x;
    if (i < N_NODES) g_cntN[i] = 0;
}
__global__ void k_hist(const int* __restrict__ ei) {
    for (int e = blockIdx.x * blockDim.x + threadIdx.x; e < N_EDGES;
         e += gridDim.x * blockDim.x)
        atomicAdd(&g_cntN[ei[N_EDGES + e]], 1);
}
#define SCAN_T 1024
#define SCAN_C 98   // 1024*98 = 100352 >= 100000
__global__ void k_scan() {
    __shared__ int ssum[SCAN_T];
    int t = threadIdx.x;
    int base = t * SCAN_C;
    int lim = (base < N_NODES) ? min(SCAN_C, N_NODES - base) : 0;
    int s = 0;
    for (int i = 0; i < lim; i++) s += g_cntN[base + i];
    ssum[t] = s;
    __syncthreads();
    for (int d = 1; d < SCAN_T; d <<= 1) {
        int w = (t >= d) ? ssum[t - d] : 0;
        __syncthreads();
        ssum[t] += w;
        __syncthreads();
    }
    int run = ssum[t] - s;  // exclusive base for this thread
    for (int i = 0; i < lim; i++) {
        int c = g_cntN[base + i];
        g_off2[base + i] = run;
        run += c;
    }
}
__global__ void k_scatter(const int* __restrict__ ei) {
    for (int e = blockIdx.x * blockDim.x + threadIdx.x; e < N_EDGES;
         e += gridDim.x * blockDim.x) {
        int dst = ei[N_EDGES + e];
        int pos = atomicAdd(&g_off2[dst], 1);
        g_esrc[pos]  = ei[e];
        g_edst[pos]  = dst;
        g_eperm[pos] = e;
    }
}

// ---------------- zero-init kernels ----------------
__global__ void k_zero_agg1() {
    int i = blockIdx.x * blockDim.x + threadIdx.x;
    if (i < N_NODES * 3) g_agg1[i] = 0.f;
}
__global__ void k_zero_pool() {
    int i = blockIdx.x * blockDim.x + threadIdx.x;
    if (i < N_GRAPHS * HIDDEN) g_pool[i] = 0.f;
    if (i < N_GRAPHS) g_cnt[i] = 0.f;
}

// ---------------- conv1: channels=3, direct per-edge ----------------
__global__ void k_conv1(const float* __restrict__ x, const int* __restrict__ ei,
                        const float* __restrict__ ea,
                        const float* __restrict__ Wf, const float* __restrict__ bf,
                        const float* __restrict__ Ws, const float* __restrict__ bs) {
    __shared__ float sWf[38 * 3], sWs[38 * 3], sbf[3], sbs[3];
    int tid = threadIdx.x;
    if (tid < 114) { sWf[tid] = Wf[tid]; sWs[tid] = Ws[tid]; }
    if (tid < 3)   { sbf[tid] = bf[tid]; sbs[tid] = bs[tid]; }
    __syncthreads();

    for (int e = blockIdx.x * blockDim.x + tid; e < N_EDGES; e += gridDim.x * blockDim.x) {
        int src = ei[e];
        int dst = ei[N_EDGES + e];
        float f[3], s[3];
#pragma unroll
        for (int c = 0; c < 3; c++) { f[c] = sbf[c]; s[c] = sbs[c]; }
#pragma unroll
        for (int i = 0; i < 3; i++) {
            float xv = x[dst * 3 + i];
#pragma unroll
            for (int c = 0; c < 3; c++) { f[c] += xv * sWf[i * 3 + c]; s[c] += xv * sWs[i * 3 + c]; }
        }
#pragma unroll
        for (int i = 0; i < 3; i++) {
            float xv = x[src * 3 + i];
#pragma unroll
            for (int c = 0; c < 3; c++) { f[c] += xv * sWf[(3 + i) * 3 + c]; s[c] += xv * sWs[(3 + i) * 3 + c]; }
        }
        const float4* ep = (const float4*)(ea + (size_t)e * 32);
#pragma unroll
        for (int q = 0; q < 8; q++) {
            float4 ev = ep[q];
            float evv[4] = {ev.x, ev.y, ev.z, ev.w};
#pragma unroll
            for (int j = 0; j < 4; j++) {
                int i = 6 + q * 4 + j;
#pragma unroll
                for (int c = 0; c < 3; c++) { f[c] += evv[j] * sWf[i * 3 + c]; s[c] += evv[j] * sWs[i * 3 + c]; }
            }
        }
#pragma unroll
        for (int c = 0; c < 3; c++) {
            float m = sigmoidf_(f[c]) * softplusf_(s[c]);
            atomicAdd(&g_agg1[dst * 3 + c], m);
        }
    }
}

// ---------------- project: h = relu((x + agg1) @ Wp + bp) ----------------
__global__ void k_project(const float* __restrict__ x, const float* __restrict__ Wp,
                          const float* __restrict__ bp) {
    int node = blockIdx.x;
    int j = threadIdx.x;  // 128
    __shared__ float xa[3];
    if (j < 3) xa[j] = x[node * 3 + j] + g_agg1[node * 3 + j];
    __syncthreads();
    float v = bp[j] + xa[0] * Wp[j] + xa[1] * Wp[128 + j] + xa[2] * Wp[256 + j];
    g_h[(size_t)node * HIDDEN + j] = fmaxf(v, 0.f);
}

// ---------------- pack Wcat[128,512] ----------------
__global__ void k_pack(const float* __restrict__ Wf, const float* __restrict__ Ws) {
    int idx = blockIdx.x * blockDim.x + threadIdx.x;
    if (idx >= 128 * 512) return;
    int k = idx >> 9, j = idx & 511;
    float v;
    if      (j < 128) v = Wf[k * 128 + j];
    else if (j < 256) v = Ws[k * 128 + (j - 128)];
    else if (j < 384) v = Wf[(k + 128) * 128 + (j - 256)];
    else              v = Ws[(k + 128) * 128 + (j - 384)];
    g_Wcat[idx] = v;
}

// ---------------- node GEMM: P[M,512] = h[M,128] @ Wcat[128,512] ----------------
__global__ void k_gemm() {
    const int M = N_NODES;
    __shared__ float2 As2[8][128];
    __shared__ float  Bs[8][128];
    int tid = threadIdx.x;
    int tx = tid & 15, ty = tid >> 4;
    int bx = blockIdx.x;
    int rowBase = blockIdx.y * 128;

    ull acc2[8][4];
#pragma unroll
    for (int i = 0; i < 8; i++)
#pragma unroll
        for (int j = 0; j < 4; j++) acc2[i][j] = 0ull;

    int arow_l = tid >> 1;
    int arow   = rowBase + arow_l;
    int acol4  = (tid & 1) * 4;
    int brow   = tid >> 5;
    int bcol4  = (tid & 31) * 4;

    for (int k0 = 0; k0 < 128; k0 += 8) {
        float4 a = (arow < M) ? *(const float4*)&g_h[(size_t)arow * 128 + k0 + acol4]
                              : make_float4(0.f, 0.f, 0.f, 0.f);
        As2[acol4 + 0][arow_l] = make_float2(a.x, a.x);
        As2[acol4 + 1][arow_l] = make_float2(a.y, a.y);
        As2[acol4 + 2][arow_l] = make_float2(a.z, a.z);
        As2[acol4 + 3][arow_l] = make_float2(a.w, a.w);
        *(float4*)&Bs[brow][bcol4] =
            *(const float4*)&g_Wcat[(k0 + brow) * 512 + bx * 128 + bcol4];
        __syncthreads();
#pragma unroll
        for (int k = 0; k < 8; k++) {
            ull a2[8];
#pragma unroll
            for (int i = 0; i < 8; i++)
                a2[i] = *(const ull*)&As2[k][ty * 8 + i];
            ulonglong2 b0 = *(const ulonglong2*)&Bs[k][tx * 8];
            ulonglong2 b1 = *(const ulonglong2*)&Bs[k][tx * 8 + 4];
#pragma unroll
            for (int i = 0; i < 8; i++) {
                acc2[i][0] = fma2(a2[i], b0.x, acc2[i][0]);
                acc2[i][1] = fma2(a2[i], b0.y, acc2[i][1]);
                acc2[i][2] = fma2(a2[i], b1.x, acc2[i][2]);
                acc2[i][3] = fma2(a2[i], b1.y, acc2[i][3]);
            }
        }
        __syncthreads();
    }
#pragma unroll
    for (int i = 0; i < 8; i++) {
        int row = rowBase + ty * 8 + i;
        if (row < M) {
            float2 v0 = upk(acc2[i][0]), v1 = upk(acc2[i][1]);
            float2 v2 = upk(acc2[i][2]), v3 = upk(acc2[i][3]);
            *(float4*)&g_P[(size_t)row * 512 + bx * 128 + tx * 8] =
                make_float4(v0.x, v0.y, v1.x, v1.y);
            *(float4*)&g_P[(size_t)row * 512 + bx * 128 + tx * 8 + 4] =
                make_float4(v2.x, v2.y, v3.x, v3.y);
        }
    }
}

// ---------------- edge kernel: dst-sorted, run-accumulated, FFMA2 ----------------
// Adds messages directly into g_h (which holds the residual h).
__global__ void __launch_bounds__(256, 2)
k_edge(const float* __restrict__ ea,
       const float* __restrict__ Wf, const float* __restrict__ Ws,
       const float* __restrict__ bf, const float* __restrict__ bs) {
    __shared__ float sWf[32 * 128];
    __shared__ float sWs[32 * 128];
    __shared__ ull   se2[8][ETILE * 32];

    int tid = threadIdx.x;  // 256
    for (int i = tid; i < 32 * 128 / 4; i += 256) {
        ((float4*)sWf)[i] = ((const float4*)(Wf + 256 * 128))[i];
        ((float4*)sWs)[i] = ((const float4*)(Ws + 256 * 128))[i];
    }
    __syncthreads();

    int warp = tid >> 5, lane = tid & 31;
    float4 bfv = *(const float4*)&bf[lane * 4];
    float4 bsv = *(const float4*)&bs[lane * 4];

    int e0 = blockIdx.x * (8 * ETILE) + warp * ETILE;  // grid sized exactly

    int vsrc = 0, vdst = 0, vprm = 0;
    if (lane < ETILE) {
        vsrc = g_esrc[e0 + lane];
        vdst = g_edst[e0 + lane];
        vprm = g_eperm[e0 + lane];
    }

    // stage edge attrs (via perm) duplicated into smem
#pragma unroll
    for (int t = 0; t < ETILE; t++) {
        int prm = __shfl_sync(0xffffffffu, vprm, t);
        float ev = __ldg(&ea[(size_t)prm * 32 + lane]);
        se2[warp][t * 32 + lane] = pk2(ev, ev);
    }

    ull fA[ETILE][2], sA[ETILE][2];
    int dsts[ETILE];
#pragma unroll
    for (int t = 0; t < ETILE; t++) {
        int src = __shfl_sync(0xffffffffu, vsrc, t);
        int dst = __shfl_sync(0xffffffffu, vdst, t);
        dsts[t] = dst;
        const float4* Pd = (const float4*)&g_P[(size_t)dst * 512];
        const float4* Ps = (const float4*)&g_P[(size_t)src * 512 + 256];
        float4 fd = __ldg(&Pd[lane]),      fs = __ldg(&Ps[lane]);
        float4 sd = __ldg(&Pd[32 + lane]), ss = __ldg(&Ps[32 + lane]);
        fA[t][0] = pk2(fd.x + fs.x + bfv.x, fd.y + fs.y + bfv.y);
        fA[t][1] = pk2(fd.z + fs.z + bfv.z, fd.w + fs.w + bfv.w);
        sA[t][0] = pk2(sd.x + ss.x + bsv.x, sd.y + ss.y + bsv.y);
        sA[t][1] = pk2(sd.z + ss.z + bsv.z, sd.w + ss.w + bsv.w);
    }
    __syncwarp();

#pragma unroll 8
    for (int k = 0; k < 32; k++) {
        ulonglong2 wf = *(const ulonglong2*)&sWf[k * 128 + lane * 4];
        ulonglong2 ws = *(const ulonglong2*)&sWs[k * 128 + lane * 4];
#pragma unroll
        for (int t = 0; t < ETILE; t++) {
            ull e2 = se2[warp][t * 32 + k];
            fA[t][0] = fma2(e2, wf.x, fA[t][0]);
            fA[t][1] = fma2(e2, wf.y, fA[t][1]);
            sA[t][0] = fma2(e2, ws.x, sA[t][0]);
            sA[t][1] = fma2(e2, ws.y, sA[t][1]);
        }
    }

    // run-accumulated epilogue: one atomic per dst-run
    float4 acc = make_float4(0.f, 0.f, 0.f, 0.f);
    int cur = dsts[0];
#pragma unroll
    for (int t = 0; t < ETILE; t++) {
        float2 f0 = upk(fA[t][0]), f1 = upk(fA[t][1]);
        float2 s0 = upk(sA[t][0]), s1 = upk(sA[t][1]);
        float4 m;
        m.x = sigmoidf_(f0.x) * softplusf_(s0.x);
        m.y = sigmoidf_(f0.y) * softplusf_(s0.y);
        m.z = sigmoidf_(f1.x) * softplusf_(s1.x);
        m.w = sigmoidf_(f1.y) * softplusf_(s1.y);
        if (dsts[t] != cur) {
            atomicAdd((float4*)&g_h[(size_t)cur * 128 + lane * 4], acc);
            acc = make_float4(0.f, 0.f, 0.f, 0.f);
            cur = dsts[t];
        }
        acc.x += m.x; acc.y += m.y; acc.z += m.z; acc.w += m.w;
    }
    atomicAdd((float4*)&g_h[(size_t)cur * 128 + lane * 4], acc);
}

// ---------------- relu in place on g_h ----------------
__global__ void k_relu() {
    int n4 = N_NODES * HIDDEN / 4;
    for (int i = blockIdx.x * blockDim.x + threadIdx.x; i < n4; i += gridDim.x * blockDim.x) {
        float4 v = ((const float4*)g_h)[i];
        v.x = fmaxf(v.x, 0.f); v.y = fmaxf(v.y, 0.f);
        v.z = fmaxf(v.z, 0.f); v.w = fmaxf(v.w, 0.f);
        ((float4*)g_h)[i] = v;
    }
}

// ---------------- mean pool (batch sorted) ----------------
#define POOL_NODES 64
__global__ void k_pool(const int* __restrict__ batch) {
    __shared__ int sb[POOL_NODES];
    int j = threadIdx.x;  // 128
    int start = blockIdx.x * POOL_NODES;
    int cnt_here = min(POOL_NODES, N_NODES - start);
    for (int i = j; i < cnt_here; i += blockDim.x) sb[i] = batch[start + i];
    __syncthreads();
    float acc = 0.f;
    int cur = sb[0];
    int run = 0;
    for (int n = 0; n < cnt_here; n++) {
        int g = sb[n];
        if (g != cur) {
            atomicAdd(&g_pool[cur * HIDDEN + j], acc);
            if (j == 0) atomicAdd(&g_cnt[cur], (float)run);
            acc = 0.f; run = 0; cur = g;
        }
        acc += g_h[(size_t)(start + n) * HIDDEN + j];
        run++;
    }
    atomicAdd(&g_pool[cur * HIDDEN + j], acc);
    if (j == 0) atomicAdd(&g_cnt[cur], (float)run);
}

// ---------------- head ----------------
__global__ void k_head(const float* __restrict__ W1, const float* __restrict__ b1,
                       const float* __restrict__ W2, const float* __restrict__ b2,
                       float* __restrict__ out) {
    int gph = blockIdx.x;
    int j = threadIdx.x;  // 128
    __shared__ float sp[128], sg[128];
    float c = fmaxf(g_cnt[gph], 1.f);
    sp[j] = g_pool[gph * 128 + j] / c;
    __syncthreads();
    float v = b1[j];
#pragma unroll 8
    for (int k = 0; k < 128; k++) v += sp[k] * W1[k * 128 + j];
    sg[j] = fmaxf(v, 0.f);
    __syncthreads();
    if (j < 3) {
        float o = b2[j];
        for (int k = 0; k < 128; k++) o += sg[k] * W2[k * 3 + j];
        out[gph * 3 + j] = o;
    }
}

// ---------------- launch ----------------
extern "C" void kernel_launch(void* const* d_in, const int* in_sizes, int n_in,
                              void* d_out, int out_size) {
    const float* x   = (const float*)d_in[0];
    const int*   ei  = (const int*)d_in[1];
    const float* ea  = (const float*)d_in[2];
    const int*   bat = (const int*)d_in[3];
    const float* Wf1 = (const float*)d_in[4];
    const float* bf1 = (const float*)d_in[5];
    const float* Ws1 = (const float*)d_in[6];
    const float* bs1 = (const float*)d_in[7];
    const float* Wp  = (const float*)d_in[8];
    const float* bp  = (const float*)d_in[9];
    const float* Wf2 = (const float*)d_in[10];
    const float* bf2 = (const float*)d_in[11];
    const float* Ws2 = (const float*)d_in[12];
    const float* bs2 = (const float*)d_in[13];
    const float* Wf3 = (const float*)d_in[14];
    const float* bf3 = (const float*)d_in[15];
    const float* Ws3 = (const float*)d_in[16];
    const float* bs3 = (const float*)d_in[17];
    const float* W1  = (const float*)d_in[18];
    const float* b1  = (const float*)d_in[19];
    const float* W2  = (const float*)d_in[20];
    const float* b2  = (const float*)d_in[21];
    float* out = (float*)d_out;

    dim3 gemm_grid(4, (N_NODES + 127) / 128);
    int edge_grid = N_EDGES / (8 * ETILE);   // 25000, exact

    // sort edges by dst (count sort)
    k_zero_cnt<<<(N_NODES + 1023) / 1024, 1024>>>();
    k_hist<<<2048, 256>>>(ei);
    k_scan<<<1, SCAN_T>>>();
    k_scatter<<<2048, 256>>>(ei);

    // conv1 (channels=3)
    k_zero_agg1<<<(N_NODES * 3 + 255) / 256, 256>>>();
    k_conv1<<<4096, 256>>>(x, ei, ea, Wf1, bf1, Ws1, bs1);
    k_project<<<N_NODES, 128>>>(x, Wp, bp);

    // conv2
    k_pack<<<256, 256>>>(Wf2, Ws2);
    k_gemm<<<gemm_grid, 256>>>();
    k_edge<<<edge_grid, 256>>>(ea, Wf2, Ws2, bf2, bs2);
    k_relu<<<4096, 256>>>();

    // conv3
    k_pack<<<256, 256>>>(Wf3, Ws3);
    k_gemm<<<gemm_grid, 256>>>();
    k_edge<<<edge_grid, 256>>>(ea, Wf3, Ws3, bf3, bs3);
    k_relu<<<4096, 256>>>();

    // pool + head
    k_zero_pool<<<(N_GRAPHS * HIDDEN + 255) / 256, 256>>>();
    k_pool<<<(N_NODES + POOL_NODES - 1) / POOL_NODES, 128>>>(bat);
    k_head<<<N_GRAPHS, 128>>>(W1, b1, W2, b2, out);
}

// round 12
// speedup vs baseline: 1.0026x; 1.0026x over previous
#include <cuda_runtime.h>
#include <math.h>

#define N_NODES 100000
#define N_EDGES 1600000
#define HIDDEN  128
#define N_GRAPHS 64
#define ETILE   8

// ---------------- device scratch (static allocs only) ----------------
__device__ float g_h   [N_NODES * HIDDEN];
__device__ float g_P   [N_NODES * 512];
__device__ float g_agg1[N_NODES * 3];
__device__ float g_Wcat[128 * 512];
__device__ float g_pool[N_GRAPHS * HIDDEN];
__device__ float g_cnt [N_GRAPHS];
// sort scratch
__device__ int g_cntN [N_NODES];
__device__ int g_off2 [N_NODES];
__device__ int g_esrc [N_EDGES];
__device__ int g_edst [N_EDGES];
__device__ int g_eperm[N_EDGES];

__device__ __forceinline__ float sigmoidf_(float x) { return 1.f / (1.f + expf(-x)); }
__device__ __forceinline__ float softplusf_(float x) {
    return fmaxf(x, 0.f) + log1pf(expf(-fabsf(x)));
}

// ---------------- packed f32x2 helpers (FFMA2) ----------------
typedef unsigned long long ull;
__device__ __forceinline__ ull pk2(float lo, float hi) {
    ull r; asm("mov.b64 %0, {%1, %2};" : "=l"(r) : "f"(lo), "f"(hi)); return r;
}
__device__ __forceinline__ ull fma2(ull a, ull b, ull c) {
    ull d; asm("fma.rn.f32x2 %0, %1, %2, %3;" : "=l"(d) : "l"(a), "l"(b), "l"(c)); return d;
}
__device__ __forceinline__ float2 upk(ull v) {
    float2 r; asm("mov.b64 {%0, %1}, %2;" : "=f"(r.x), "=f"(r.y) : "l"(v)); return r;
}

// ---------------- sort: count-sort edges by dst ----------------
__global__ void k_zero_cnt() {
    int i = blockIdx.x * blockDim.x + threadIdx.x;
    if (i < N_NODES) g_cntN[i] = 0;
}
__global__ void k_hist(const int* __restrict__ ei) {
    for (int e = blockIdx.x * blockDim.x + threadIdx.x; e < N_EDGES;
         e += gridDim.x * blockDim.x)
        atomicAdd(&g_cntN[ei[N_EDGES + e]], 1);
}
#define SCAN_T 1024
#define SCAN_C 98   // 1024*98 = 100352 >= 100000
__global__ void k_scan() {
    __shared__ int ssum[SCAN_T];
    int t = threadIdx.x;
    int base = t * SCAN_C;
    int lim = (base < N_NODES) ? min(SCAN_C, N_NODES - base) : 0;
    int s = 0;
    for (int i = 0; i < lim; i++) s += g_cntN[base + i];
    ssum[t] = s;
    __syncthreads();
    for (int d = 1; d < SCAN_T; d <<= 1) {
        int w = (t >= d) ? ssum[t - d] : 0;
        __syncthreads();
        ssum[t] += w;
        __syncthreads();
    }
    int run = ssum[t] - s;  // exclusive base for this thread
    for (int i = 0; i < lim; i++) {
        int c = g_cntN[base + i];
        g_off2[base + i] = run;
        run += c;
    }
}
__global__ void k_scatter(const int* __restrict__ ei) {
    for (int e = blockIdx.x * blockDim.x + threadIdx.x; e < N_EDGES;
         e += gridDim.x * blockDim.x) {
        int dst = ei[N_EDGES + e];
        int pos = atomicAdd(&g_off2[dst], 1);
        g_esrc[pos]  = ei[e];
        g_edst[pos]  = dst;
        g_eperm[pos] = e;
    }
}

// ---------------- zero-init kernels ----------------
__global__ void k_zero_agg1() {
    int i = blockIdx.x * blockDim.x + threadIdx.x;
    if (i < N_NODES * 3) g_agg1[i] = 0.f;
}
__global__ void k_zero_pool() {
    int i = blockIdx.x * blockDim.x + threadIdx.x;
    if (i < N_GRAPHS * HIDDEN) g_pool[i] = 0.f;
    if (i < N_GRAPHS) g_cnt[i] = 0.f;
}

// ---------------- conv1: channels=3, direct per-edge ----------------
__global__ void k_conv1(const float* __restrict__ x, const int* __restrict__ ei,
                        const float* __restrict__ ea,
                        const float* __restrict__ Wf, const float* __restrict__ bf,
                        const float* __restrict__ Ws, const float* __restrict__ bs) {
    __shared__ float sWf[38 * 3], sWs[38 * 3], sbf[3], sbs[3];
    int tid = threadIdx.x;
    if (tid < 114) { sWf[tid] = Wf[tid]; sWs[tid] = Ws[tid]; }
    if (tid < 3)   { sbf[tid] = bf[tid]; sbs[tid] = bs[tid]; }
    __syncthreads();

    for (int e = blockIdx.x * blockDim.x + tid; e < N_EDGES; e += gridDim.x * blockDim.x) {
        int src = ei[e];
        int dst = ei[N_EDGES + e];
        float f[3], s[3];
#pragma unroll
        for (int c = 0; c < 3; c++) { f[c] = sbf[c]; s[c] = sbs[c]; }
#pragma unroll
        for (int i = 0; i < 3; i++) {
            float xv = x[dst * 3 + i];
#pragma unroll
            for (int c = 0; c < 3; c++) { f[c] += xv * sWf[i * 3 + c]; s[c] += xv * sWs[i * 3 + c]; }
        }
#pragma unroll
        for (int i = 0; i < 3; i++) {
            float xv = x[src * 3 + i];
#pragma unroll
            for (int c = 0; c < 3; c++) { f[c] += xv * sWf[(3 + i) * 3 + c]; s[c] += xv * sWs[(3 + i) * 3 + c]; }
        }
        const float4* ep = (const float4*)(ea + (size_t)e * 32);
#pragma unroll
        for (int q = 0; q < 8; q++) {
            float4 ev = ep[q];
            float evv[4] = {ev.x, ev.y, ev.z, ev.w};
#pragma unroll
            for (int j = 0; j < 4; j++) {
                int i = 6 + q * 4 + j;
#pragma unroll
                for (int c = 0; c < 3; c++) { f[c] += evv[j] * sWf[i * 3 + c]; s[c] += evv[j] * sWs[i * 3 + c]; }
            }
        }
#pragma unroll
        for (int c = 0; c < 3; c++) {
            float m = sigmoidf_(f[c]) * softplusf_(s[c]);
            atomicAdd(&g_agg1[dst * 3 + c], m);
        }
    }
}

// ---------------- project: h = relu((x + agg1) @ Wp + bp) ----------------
__global__ void k_project(const float* __restrict__ x, const float* __restrict__ Wp,
                          const float* __restrict__ bp) {
    int node = blockIdx.x;
    int j = threadIdx.x;  // 128
    __shared__ float xa[3];
    if (j < 3) xa[j] = x[node * 3 + j] + g_agg1[node * 3 + j];
    __syncthreads();
    float v = bp[j] + xa[0] * Wp[j] + xa[1] * Wp[128 + j] + xa[2] * Wp[256 + j];
    g_h[(size_t)node * HIDDEN + j] = fmaxf(v, 0.f);
}

// ---------------- pack Wcat[128,512] ----------------
__global__ void k_pack(const float* __restrict__ Wf, const float* __restrict__ Ws) {
    int idx = blockIdx.x * blockDim.x + threadIdx.x;
    if (idx >= 128 * 512) return;
    int k = idx >> 9, j = idx & 511;
    float v;
    if      (j < 128) v = Wf[k * 128 + j];
    else if (j < 256) v = Ws[k * 128 + (j - 128)];
    else if (j < 384) v = Wf[(k + 128) * 128 + (j - 256)];
    else              v = Ws[(k + 128) * 128 + (j - 384)];
    g_Wcat[idx] = v;
}

// ---------------- node GEMM: P[M,512] = h[M,128] @ Wcat[128,512] ----------------
__global__ void k_gemm() {
    const int M = N_NODES;
    __shared__ float2 As2[8][128];
    __shared__ float  Bs[8][128];
    int tid = threadIdx.x;
    int tx = tid & 15, ty = tid >> 4;
    int bx = blockIdx.x;
    int rowBase = blockIdx.y * 128;

    ull acc2[8][4];
#pragma unroll
    for (int i = 0; i < 8; i++)
#pragma unroll
        for (int j = 0; j < 4; j++) acc2[i][j] = 0ull;

    int arow_l = tid >> 1;
    int arow   = rowBase + arow_l;
    int acol4  = (tid & 1) * 4;
    int brow   = tid >> 5;
    int bcol4  = (tid & 31) * 4;

    for (int k0 = 0; k0 < 128; k0 += 8) {
        float4 a = (arow < M) ? *(const float4*)&g_h[(size_t)arow * 128 + k0 + acol4]
                              : make_float4(0.f, 0.f, 0.f, 0.f);
        As2[acol4 + 0][arow_l] = make_float2(a.x, a.x);
        As2[acol4 + 1][arow_l] = make_float2(a.y, a.y);
        As2[acol4 + 2][arow_l] = make_float2(a.z, a.z);
        As2[acol4 + 3][arow_l] = make_float2(a.w, a.w);
        *(float4*)&Bs[brow][bcol4] =
            *(const float4*)&g_Wcat[(k0 + brow) * 512 + bx * 128 + bcol4];
        __syncthreads();
#pragma unroll
        for (int k = 0; k < 8; k++) {
            ull a2[8];
#pragma unroll
            for (int i = 0; i < 8; i++)
                a2[i] = *(const ull*)&As2[k][ty * 8 + i];
            ulonglong2 b0 = *(const ulonglong2*)&Bs[k][tx * 8];
            ulonglong2 b1 = *(const ulonglong2*)&Bs[k][tx * 8 + 4];
#pragma unroll
            for (int i = 0; i < 8; i++) {
                acc2[i][0] = fma2(a2[i], b0.x, acc2[i][0]);
                acc2[i][1] = fma2(a2[i], b0.y, acc2[i][1]);
                acc2[i][2] = fma2(a2[i], b1.x, acc2[i][2]);
                acc2[i][3] = fma2(a2[i], b1.y, acc2[i][3]);
            }
        }
        __syncthreads();
    }
#pragma unroll
    for (int i = 0; i < 8; i++) {
        int row = rowBase + ty * 8 + i;
        if (row < M) {
            float2 v0 = upk(acc2[i][0]), v1 = upk(acc2[i][1]);
            float2 v2 = upk(acc2[i][2]), v3 = upk(acc2[i][3]);
            *(float4*)&g_P[(size_t)row * 512 + bx * 128 + tx * 8] =
                make_float4(v0.x, v0.y, v1.x, v1.y);
            *(float4*)&g_P[(size_t)row * 512 + bx * 128 + tx * 8 + 4] =
                make_float4(v2.x, v2.y, v3.x, v3.y);
        }
    }
}

// ---------------- edge kernel: dst-sorted, run-accumulated, FFMA2 ----------------
// Adds messages directly into g_h (which holds the residual h).
__global__ void __launch_bounds__(256, 2)
k_edge(const float* __restrict__ ea,
       const float* __restrict__ Wf, const float* __restrict__ Ws,
       const float* __restrict__ bf, const float* __restrict__ bs) {
    __shared__ float sWf[32 * 128];
    __shared__ float sWs[32 * 128];
    __shared__ ull   se2[8][ETILE * 32];

    int tid = threadIdx.x;  // 256
    for (int i = tid; i < 32 * 128 / 4; i += 256) {
        ((float4*)sWf)[i] = ((const float4*)(Wf + 256 * 128))[i];
        ((float4*)sWs)[i] = ((const float4*)(Ws + 256 * 128))[i];
    }
    __syncthreads();

    int warp = tid >> 5, lane = tid & 31;
    float4 bfv = *(const float4*)&bf[lane * 4];
    float4 bsv = *(const float4*)&bs[lane * 4];

    int e0 = blockIdx.x * (8 * ETILE) + warp * ETILE;  // grid sized exactly

    int vsrc = 0, vdst = 0, vprm = 0;
    if (lane < ETILE) {
        vsrc = g_esrc[e0 + lane];
        vdst = g_edst[e0 + lane];
        vprm = g_eperm[e0 + lane];
    }

    // stage edge attrs (via perm) duplicated into smem
#pragma unroll
    for (int t = 0; t < ETILE; t++) {
        int prm = __shfl_sync(0xffffffffu, vprm, t);
        float ev = __ldg(&ea[(size_t)prm * 32 + lane]);
        se2[warp][t * 32 + lane] = pk2(ev, ev);
    }

    ull fA[ETILE][2], sA[ETILE][2];
    int dsts[ETILE];
#pragma unroll
    for (int t = 0; t < ETILE; t++) {
        int src = __shfl_sync(0xffffffffu, vsrc, t);
        int dst = __shfl_sync(0xffffffffu, vdst, t);
        dsts[t] = dst;
        const float4* Pd = (const float4*)&g_P[(size_t)dst * 512];
        const float4* Ps = (const float4*)&g_P[(size_t)src * 512 + 256];
        float4 fd = __ldg(&Pd[lane]),      fs = __ldg(&Ps[lane]);
        float4 sd = __ldg(&Pd[32 + lane]), ss = __ldg(&Ps[32 + lane]);
        fA[t][0] = pk2(fd.x + fs.x + bfv.x, fd.y + fs.y + bfv.y);
        fA[t][1] = pk2(fd.z + fs.z + bfv.z, fd.w + fs.w + bfv.w);
        sA[t][0] = pk2(sd.x + ss.x + bsv.x, sd.y + ss.y + bsv.y);
        sA[t][1] = pk2(sd.z + ss.z + bsv.z, sd.w + ss.w + bsv.w);
    }
    __syncwarp();

#pragma unroll 8
    for (int k = 0; k < 32; k++) {
        ulonglong2 wf = *(const ulonglong2*)&sWf[k * 128 + lane * 4];
        ulonglong2 ws = *(const ulonglong2*)&sWs[k * 128 + lane * 4];
#pragma unroll
        for (int t = 0; t < ETILE; t++) {
            ull e2 = se2[warp][t * 32 + k];
            fA[t][0] = fma2(e2, wf.x, fA[t][0]);
            fA[t][1] = fma2(e2, wf.y, fA[t][1]);
            sA[t][0] = fma2(e2, ws.x, sA[t][0]);
            sA[t][1] = fma2(e2, ws.y, sA[t][1]);
        }
    }

    // run-accumulated epilogue: one atomic per dst-run
    float4 acc = make_float4(0.f, 0.f, 0.f, 0.f);
    int cur = dsts[0];
#pragma unroll
    for (int t = 0; t < ETILE; t++) {
        float2 f0 = upk(fA[t][0]), f1 = upk(fA[t][1]);
        float2 s0 = upk(sA[t][0]), s1 = upk(sA[t][1]);
        float4 m;
        m.x = sigmoidf_(f0.x) * softplusf_(s0.x);
        m.y = sigmoidf_(f0.y) * softplusf_(s0.y);
        m.z = sigmoidf_(f1.x) * softplusf_(s1.x);
        m.w = sigmoidf_(f1.y) * softplusf_(s1.y);
        if (dsts[t] != cur) {
            atomicAdd((float4*)&g_h[(size_t)cur * 128 + lane * 4], acc);
            acc = make_float4(0.f, 0.f, 0.f, 0.f);
            cur = dsts[t];
        }
        acc.x += m.x; acc.y += m.y; acc.z += m.z; acc.w += m.w;
    }
    atomicAdd((float4*)&g_h[(size_t)cur * 128 + lane * 4], acc);
}

// ---------------- relu in place on g_h ----------------
__global__ void k_relu() {
    int n4 = N_NODES * HIDDEN / 4;
    for (int i = blockIdx.x * blockDim.x + threadIdx.x; i < n4; i += gridDim.x * blockDim.x) {
        float4 v = ((const float4*)g_h)[i];
        v.x = fmaxf(v.x, 0.f); v.y = fmaxf(v.y, 0.f);
        v.z = fmaxf(v.z, 0.f); v.w = fmaxf(v.w, 0.f);
        ((float4*)g_h)[i] = v;
    }
}

// ---------------- mean pool (batch sorted) ----------------
#define POOL_NODES 64
__global__ void k_pool(const int* __restrict__ batch) {
    __shared__ int sb[POOL_NODES];
    int j = threadIdx.x;  // 128
    int start = blockIdx.x * POOL_NODES;
    int cnt_here = min(POOL_NODES, N_NODES - start);
    for (int i = j; i < cnt_here; i += blockDim.x) sb[i] = batch[start + i];
    __syncthreads();
    float acc = 0.f;
    int cur = sb[0];
    int run = 0;
    for (int n = 0; n < cnt_here; n++) {
        int g = sb[n];
        if (g != cur) {
            atomicAdd(&g_pool[cur * HIDDEN + j], acc);
            if (j == 0) atomicAdd(&g_cnt[cur], (float)run);
            acc = 0.f; run = 0; cur = g;
        }
        acc += g_h[(size_t)(start + n) * HIDDEN + j];
        run++;
    }
    atomicAdd(&g_pool[cur * HIDDEN + j], acc);
    if (j == 0) atomicAdd(&g_cnt[cur], (float)run);
}

// ---------------- head ----------------
__global__ void k_head(const float* __restrict__ W1, const float* __restrict__ b1,
                       const float* __restrict__ W2, const float* __restrict__ b2,
                       float* __restrict__ out) {
    int gph = blockIdx.x;
    int j = threadIdx.x;  // 128
    __shared__ float sp[128], sg[128];
    float c = fmaxf(g_cnt[gph], 1.f);
    sp[j] = g_pool[gph * 128 + j] / c;
    __syncthreads();
    float v = b1[j];
#pragma unroll 8
    for (int k = 0; k < 128; k++) v += sp[k] * W1[k * 128 + j];
    sg[j] = fmaxf(v, 0.f);
    __syncthreads();
    if (j < 3) {
        float o = b2[j];
        for (int k = 0; k < 128; k++) o += sg[k] * W2[k * 3 + j];
        out[gph * 3 + j] = o;
    }
}

// ---------------- launch ----------------
extern "C" void kernel_launch(void* const* d_in, const int* in_sizes, int n_in,
                              void* d_out, int out_size) {
    const float* x   = (const float*)d_in[0];
    const int*   ei  = (const int*)d_in[1];
    const float* ea  = (const float*)d_in[2];
    const int*   bat = (const int*)d_in[3];
    const float* Wf1 = (const float*)d_in[4];
    const float* bf1 = (const float*)d_in[5];
    const float* Ws1 = (const float*)d_in[6];
    const float* bs1 = (const float*)d_in[7];
    const float* Wp  = (const float*)d_in[8];
    const float* bp  = (const float*)d_in[9];
    const float* Wf2 = (const float*)d_in[10];
    const float* bf2 = (const float*)d_in[11];
    const float* Ws2 = (const float*)d_in[12];
    const float* bs2 = (const float*)d_in[13];
    const float* Wf3 = (const float*)d_in[14];
    const float* bf3 = (const float*)d_in[15];
    const float* Ws3 = (const float*)d_in[16];
    const float* bs3 = (const float*)d_in[17];
    const float* W1  = (const float*)d_in[18];
    const float* b1  = (const float*)d_in[19];
    const float* W2  = (const float*)d_in[20];
    const float* b2  = (const float*)d_in[21];
    float* out = (float*)d_out;

    dim3 gemm_grid(4, (N_NODES + 127) / 128);
    int edge_grid = N_EDGES / (8 * ETILE);   // 25000, exact

    // sort edges by dst (count sort)
    k_zero_cnt<<<(N_NODES + 1023) / 1024, 1024>>>();
    k_hist<<<2048, 256>>>(ei);
    k_scan<<<1, SCAN_T>>>();
    k_scatter<<<2048, 256>>>(ei);

    // conv1 (channels=3)
    k_zero_agg1<<<(N_NODES * 3 + 255) / 256, 256>>>();
    k_conv1<<<4096, 256>>>(x, ei, ea, Wf1, bf1, Ws1, bs1);
    k_project<<<N_NODES, 128>>>(x, Wp, bp);

    // conv2
    k_pack<<<256, 256>>>(Wf2, Ws2);
    k_gemm<<<gemm_grid, 256>>>();
    k_edge<<<edge_grid, 256>>>(ea, Wf2, Ws2, bf2, bs2);
    k_relu<<<4096, 256>>>();

    // conv3
    k_pack<<<256, 256>>>(Wf3, Ws3);
    k_gemm<<<gemm_grid, 256>>>();
    k_edge<<<edge_grid, 256>>>(ea, Wf3, Ws3, bf3, bs3);
    k_relu<<<4096, 256>>>();

    // pool + head
    k_zero_pool<<<(N_GRAPHS * HIDDEN + 255) / 256, 256>>>();
    k_pool<<<(N_NODES + POOL_NODES - 1) / POOL_NODES, 128>>>(bat);
    k_head<<<N_GRAPHS, 128>>>(W1, b1, W2, b2, out);
}

// round 13
// speedup vs baseline: 1.2793x; 1.2759x over previous
#include <cuda_runtime.h>
#include <cuda_fp16.h>
#include <math.h>

#define N_NODES 100000
#define N_EDGES 1600000
#define HIDDEN  128
#define N_GRAPHS 64
#define ETILE   8

// ---------------- device scratch (static allocs only) ----------------
__device__ float  g_h   [N_NODES * HIDDEN];
__device__ __half g_P   [N_NODES * 512];       // 102.4 MB -> L2-resident
__device__ float  g_agg1[N_NODES * 3];
__device__ float  g_Wcat[128 * 512];
__device__ float  g_pool[N_GRAPHS * HIDDEN];
__device__ float  g_cnt [N_GRAPHS];
// sort scratch
__device__ int g_cntN [N_NODES];
__device__ int g_off2 [N_NODES];
__device__ int g_esrc [N_EDGES];
__device__ int g_edst [N_EDGES];
__device__ int g_eperm[N_EDGES];

// fast gates: __expf/__logf are MUFU-based; error ~2ulp, fine at 1e-3 tol
__device__ __forceinline__ float sigmoidf_(float x) {
    return __fdividef(1.f, 1.f + __expf(-x));
}
__device__ __forceinline__ float softplusf_(float x) {
    return fmaxf(x, 0.f) + __logf(1.f + __expf(-fabsf(x)));
}

// ---------------- packed f32x2 helpers (FFMA2) ----------------
typedef unsigned long long ull;
__device__ __forceinline__ ull pk2(float lo, float hi) {
    ull r; asm("mov.b64 %0, {%1, %2};" : "=l"(r) : "f"(lo), "f"(hi)); return r;
}
__device__ __forceinline__ ull fma2(ull a, ull b, ull c) {
    ull d; asm("fma.rn.f32x2 %0, %1, %2, %3;" : "=l"(d) : "l"(a), "l"(b), "l"(c)); return d;
}
__device__ __forceinline__ float2 upk(ull v) {
    float2 r; asm("mov.b64 {%0, %1}, %2;" : "=f"(r.x), "=f"(r.y) : "l"(v)); return r;
}

// ---------------- sort: count-sort edges by dst ----------------
__global__ void k_zero_cnt() {
    int i = blockIdx.x * blockDim.x + threadIdx.x;
    if (i < N_NODES) g_cntN[i] = 0;
}
__global__ void k_hist(const int* __restrict__ ei) {
    for (int e = blockIdx.x * blockDim.x + threadIdx.x; e < N_EDGES;
         e += gridDim.x * blockDim.x)
        atomicAdd(&g_cntN[ei[N_EDGES + e]], 1);
}
#define SCAN_T 1024
#define SCAN_C 98
__global__ void k_scan() {
    __shared__ int ssum[SCAN_T];
    int t = threadIdx.x;
    int base = t * SCAN_C;
    int lim = (base < N_NODES) ? min(SCAN_C, N_NODES - base) : 0;
    int s = 0;
    for (int i = 0; i < lim; i++) s += g_cntN[base + i];
    ssum[t] = s;
    __syncthreads();
    for (int d = 1; d < SCAN_T; d <<= 1) {
        int w = (t >= d) ? ssum[t - d] : 0;
        __syncthreads();
        ssum[t] += w;
        __syncthreads();
    }
    int run = ssum[t] - s;
    for (int i = 0; i < lim; i++) {
        int c = g_cntN[base + i];
        g_off2[base + i] = run;
        run += c;
    }
}
__global__ void k_scatter(const int* __restrict__ ei) {
    for (int e = blockIdx.x * blockDim.x + threadIdx.x; e < N_EDGES;
         e += gridDim.x * blockDim.x) {
        int dst = ei[N_EDGES + e];
        int pos = atomicAdd(&g_off2[dst], 1);
        g_esrc[pos]  = ei[e];
        g_edst[pos]  = dst;
        g_eperm[pos] = e;
    }
}

// ---------------- zero-init kernels ----------------
__global__ void k_zero_agg1() {
    int i = blockIdx.x * blockDim.x + threadIdx.x;
    if (i < N_NODES * 3) g_agg1[i] = 0.f;
}
__global__ void k_zero_pool() {
    int i = blockIdx.x * blockDim.x + threadIdx.x;
    if (i < N_GRAPHS * HIDDEN) g_pool[i] = 0.f;
    if (i < N_GRAPHS) g_cnt[i] = 0.f;
}

// ---------------- conv1: channels=3, direct per-edge ----------------
__global__ void k_conv1(const float* __restrict__ x, const int* __restrict__ ei,
                        const float* __restrict__ ea,
                        const float* __restrict__ Wf, const float* __restrict__ bf,
                        const float* __restrict__ Ws, const float* __restrict__ bs) {
    __shared__ float sWf[38 * 3], sWs[38 * 3], sbf[3], sbs[3];
    int tid = threadIdx.x;
    if (tid < 114) { sWf[tid] = Wf[tid]; sWs[tid] = Ws[tid]; }
    if (tid < 3)   { sbf[tid] = bf[tid]; sbs[tid] = bs[tid]; }
    __syncthreads();

    for (int e = blockIdx.x * blockDim.x + tid; e < N_EDGES; e += gridDim.x * blockDim.x) {
        int src = ei[e];
        int dst = ei[N_EDGES + e];
        float f[3], s[3];
#pragma unroll
        for (int c = 0; c < 3; c++) { f[c] = sbf[c]; s[c] = sbs[c]; }
#pragma unroll
        for (int i = 0; i < 3; i++) {
            float xv = x[dst * 3 + i];
#pragma unroll
            for (int c = 0; c < 3; c++) { f[c] += xv * sWf[i * 3 + c]; s[c] += xv * sWs[i * 3 + c]; }
        }
#pragma unroll
        for (int i = 0; i < 3; i++) {
            float xv = x[src * 3 + i];
#pragma unroll
            for (int c = 0; c < 3; c++) { f[c] += xv * sWf[(3 + i) * 3 + c]; s[c] += xv * sWs[(3 + i) * 3 + c]; }
        }
        const float4* ep = (const float4*)(ea + (size_t)e * 32);
#pragma unroll
        for (int q = 0; q < 8; q++) {
            float4 ev = ep[q];
            float evv[4] = {ev.x, ev.y, ev.z, ev.w};
#pragma unroll
            for (int j = 0; j < 4; j++) {
                int i = 6 + q * 4 + j;
#pragma unroll
                for (int c = 0; c < 3; c++) { f[c] += evv[j] * sWf[i * 3 + c]; s[c] += evv[j] * sWs[i * 3 + c]; }
            }
        }
#pragma unroll
        for (int c = 0; c < 3; c++) {
            float m = sigmoidf_(f[c]) * softplusf_(s[c]);
            atomicAdd(&g_agg1[dst * 3 + c], m);
        }
    }
}

// ---------------- project: h = relu((x + agg1) @ Wp + bp) ----------------
__global__ void k_project(const float* __restrict__ x, const float* __restrict__ Wp,
                          const float* __restrict__ bp) {
    int node = blockIdx.x;
    int j = threadIdx.x;  // 128
    __shared__ float xa[3];
    if (j < 3) xa[j] = x[node * 3 + j] + g_agg1[node * 3 + j];
    __syncthreads();
    float v = bp[j] + xa[0] * Wp[j] + xa[1] * Wp[128 + j] + xa[2] * Wp[256 + j];
    g_h[(size_t)node * HIDDEN + j] = fmaxf(v, 0.f);
}

// ---------------- pack Wcat[128,512] ----------------
__global__ void k_pack(const float* __restrict__ Wf, const float* __restrict__ Ws) {
    int idx = blockIdx.x * blockDim.x + threadIdx.x;
    if (idx >= 128 * 512) return;
    int k = idx >> 9, j = idx & 511;
    float v;
    if      (j < 128) v = Wf[k * 128 + j];
    else if (j < 256) v = Ws[k * 128 + (j - 128)];
    else if (j < 384) v = Wf[(k + 128) * 128 + (j - 256)];
    else              v = Ws[(k + 128) * 128 + (j - 384)];
    g_Wcat[idx] = v;
}

// ---------------- node GEMM: P[M,512] = h[M,128] @ Wcat[128,512] (fp16 out) ---
__global__ void k_gemm() {
    const int M = N_NODES;
    __shared__ float2 As2[8][128];
    __shared__ float  Bs[8][128];
    int tid = threadIdx.x;
    int tx = tid & 15, ty = tid >> 4;
    int bx = blockIdx.x;
    int rowBase = blockIdx.y * 128;

    ull acc2[8][4];
#pragma unroll
    for (int i = 0; i < 8; i++)
#pragma unroll
        for (int j = 0; j < 4; j++) acc2[i][j] = 0ull;

    int arow_l = tid >> 1;
    int arow   = rowBase + arow_l;
    int acol4  = (tid & 1) * 4;
    int brow   = tid >> 5;
    int bcol4  = (tid & 31) * 4;

    for (int k0 = 0; k0 < 128; k0 += 8) {
        float4 a = (arow < M) ? *(const float4*)&g_h[(size_t)arow * 128 + k0 + acol4]
                              : make_float4(0.f, 0.f, 0.f, 0.f);
        As2[acol4 + 0][arow_l] = make_float2(a.x, a.x);
        As2[acol4 + 1][arow_l] = make_float2(a.y, a.y);
        As2[acol4 + 2][arow_l] = make_float2(a.z, a.z);
        As2[acol4 + 3][arow_l] = make_float2(a.w, a.w);
        *(float4*)&Bs[brow][bcol4] =
            *(const float4*)&g_Wcat[(k0 + brow) * 512 + bx * 128 + bcol4];
        __syncthreads();
#pragma unroll
        for (int k = 0; k < 8; k++) {
            ull a2[8];
#pragma unroll
            for (int i = 0; i < 8; i++)
                a2[i] = *(const ull*)&As2[k][ty * 8 + i];
            ulonglong2 b0 = *(const ulonglong2*)&Bs[k][tx * 8];
            ulonglong2 b1 = *(const ulonglong2*)&Bs[k][tx * 8 + 4];
#pragma unroll
            for (int i = 0; i < 8; i++) {
                acc2[i][0] = fma2(a2[i], b0.x, acc2[i][0]);
                acc2[i][1] = fma2(a2[i], b0.y, acc2[i][1]);
                acc2[i][2] = fma2(a2[i], b1.x, acc2[i][2]);
                acc2[i][3] = fma2(a2[i], b1.y, acc2[i][3]);
            }
        }
        __syncthreads();
    }
#pragma unroll
    for (int i = 0; i < 8; i++) {
        int row = rowBase + ty * 8 + i;
        if (row < M) {
            float2 v0 = upk(acc2[i][0]), v1 = upk(acc2[i][1]);
            float2 v2 = upk(acc2[i][2]), v3 = upk(acc2[i][3]);
            __half2 h0 = __float22half2_rn(v0);
            __half2 h1 = __float22half2_rn(v1);
            __half2 h2 = __float22half2_rn(v2);
            __half2 h3 = __float22half2_rn(v3);
            uint4 pk;
            pk.x = *(unsigned*)&h0; pk.y = *(unsigned*)&h1;
            pk.z = *(unsigned*)&h2; pk.w = *(unsigned*)&h3;
            *(uint4*)&g_P[(size_t)row * 512 + bx * 128 + tx * 8] = pk;
        }
    }
}

// ---------------- edge kernel: dst-sorted, fp16 P gather, FFMA2 ----------------
__global__ void __launch_bounds__(256, 2)
k_edge(const float* __restrict__ ea,
       const float* __restrict__ Wf, const float* __restrict__ Ws,
       const float* __restrict__ bf, const float* __restrict__ bs) {
    __shared__ float sWf[32 * 128];
    __shared__ float sWs[32 * 128];
    __shared__ ull   se2[8][ETILE * 32];

    int tid = threadIdx.x;  // 256
    for (int i = tid; i < 32 * 128 / 4; i += 256) {
        ((float4*)sWf)[i] = ((const float4*)(Wf + 256 * 128))[i];
        ((float4*)sWs)[i] = ((const float4*)(Ws + 256 * 128))[i];
    }
    __syncthreads();

    int warp = tid >> 5, lane = tid & 31;
    float4 bfv = *(const float4*)&bf[lane * 4];
    float4 bsv = *(const float4*)&bs[lane * 4];

    int e0 = blockIdx.x * (8 * ETILE) + warp * ETILE;

    int vsrc = 0, vdst = 0, vprm = 0;
    if (lane < ETILE) {
        vsrc = g_esrc[e0 + lane];
        vdst = g_edst[e0 + lane];
        vprm = g_eperm[e0 + lane];
    }

#pragma unroll
    for (int t = 0; t < ETILE; t++) {
        int prm = __shfl_sync(0xffffffffu, vprm, t);
        float ev = __ldg(&ea[(size_t)prm * 32 + lane]);
        se2[warp][t * 32 + lane] = pk2(ev, ev);
    }

    ull fA[ETILE][2], sA[ETILE][2];
    int dsts[ETILE];
#pragma unroll
    for (int t = 0; t < ETILE; t++) {
        int src = __shfl_sync(0xffffffffu, vsrc, t);
        int dst = __shfl_sync(0xffffffffu, vdst, t);
        dsts[t] = dst;
        // fp16 P rows: [f_dst 128 | s_dst 128 | f_src 128 | s_src 128] halves
        const uint2* Pd = (const uint2*)&g_P[(size_t)dst * 512];
        const uint2* Ps = (const uint2*)&g_P[(size_t)src * 512 + 256];
        uint2 fd2 = __ldg(&Pd[lane]);      // 4 halves
        uint2 sd2 = __ldg(&Pd[32 + lane]);
        uint2 fs2 = __ldg(&Ps[lane]);
        uint2 ss2 = __ldg(&Ps[32 + lane]);
        float2 fd01 = __half22float2(*(const __half2*)&fd2.x);
        float2 fd23 = __half22float2(*(const __half2*)&fd2.y);
        float2 sd01 = __half22float2(*(const __half2*)&sd2.x);
        float2 sd23 = __half22float2(*(const __half2*)&sd2.y);
        float2 fs01 = __half22float2(*(const __half2*)&fs2.x);
        float2 fs23 = __half22float2(*(const __half2*)&fs2.y);
        float2 ss01 = __half22float2(*(const __half2*)&ss2.x);
        float2 ss23 = __half22float2(*(const __half2*)&ss2.y);
        fA[t][0] = pk2(fd01.x + fs01.x + bfv.x, fd01.y + fs01.y + bfv.y);
        fA[t][1] = pk2(fd23.x + fs23.x + bfv.z, fd23.y + fs23.y + bfv.w);
        sA[t][0] = pk2(sd01.x + ss01.x + bsv.x, sd01.y + ss01.y + bsv.y);
        sA[t][1] = pk2(sd23.x + ss23.x + bsv.z, sd23.y + ss23.y + bsv.w);
    }
    __syncwarp();

#pragma unroll 8
    for (int k = 0; k < 32; k++) {
        ulonglong2 wf = *(const ulonglong2*)&sWf[k * 128 + lane * 4];
        ulonglong2 ws = *(const ulonglong2*)&sWs[k * 128 + lane * 4];
#pragma unroll
        for (int t = 0; t < ETILE; t++) {
            ull e2 = se2[warp][t * 32 + k];
            fA[t][0] = fma2(e2, wf.x, fA[t][0]);
            fA[t][1] = fma2(e2, wf.y, fA[t][1]);
            sA[t][0] = fma2(e2, ws.x, sA[t][0]);
            sA[t][1] = fma2(e2, ws.y, sA[t][1]);
        }
    }

    // run-accumulated epilogue: one atomic per dst-run
    float4 acc = make_float4(0.f, 0.f, 0.f, 0.f);
    int cur = dsts[0];
#pragma unroll
    for (int t = 0; t < ETILE; t++) {
        float2 f0 = upk(fA[t][0]), f1 = upk(fA[t][1]);
        float2 s0 = upk(sA[t][0]), s1 = upk(sA[t][1]);
        float4 m;
        m.x = sigmoidf_(f0.x) * softplusf_(s0.x);
        m.y = sigmoidf_(f0.y) * softplusf_(s0.y);
        m.z = sigmoidf_(f1.x) * softplusf_(s1.x);
        m.w = sigmoidf_(f1.y) * softplusf_(s1.y);
        if (dsts[t] != cur) {
            atomicAdd((float4*)&g_h[(size_t)cur * 128 + lane * 4], acc);
            acc = make_float4(0.f, 0.f, 0.f, 0.f);
            cur = dsts[t];
        }
        acc.x += m.x; acc.y += m.y; acc.z += m.z; acc.w += m.w;
    }
    atomicAdd((float4*)&g_h[(size_t)cur * 128 + lane * 4], acc);
}

// ---------------- relu in place on g_h ----------------
__global__ void k_relu() {
    int n4 = N_NODES * HIDDEN / 4;
    for (int i = blockIdx.x * blockDim.x + threadIdx.x; i < n4; i += gridDim.x * blockDim.x) {
        float4 v = ((const float4*)g_h)[i];
        v.x = fmaxf(v.x, 0.f); v.y = fmaxf(v.y, 0.f);
        v.z = fmaxf(v.z, 0.f); v.w = fmaxf(v.w, 0.f);
        ((float4*)g_h)[i] = v;
    }
}

// ---------------- mean pool (batch sorted) ----------------
#define POOL_NODES 64
__global__ void k_pool(const int* __restrict__ batch) {
    __shared__ int sb[POOL_NODES];
    int j = threadIdx.x;  // 128
    int start = blockIdx.x * POOL_NODES;
    int cnt_here = min(POOL_NODES, N_NODES - start);
    for (int i = j; i < cnt_here; i += blockDim.x) sb[i] = batch[start + i];
    __syncthreads();
    float acc = 0.f;
    int cur = sb[0];
    int run = 0;
    for (int n = 0; n < cnt_here; n++) {
        int g = sb[n];
        if (g != cur) {
            atomicAdd(&g_pool[cur * HIDDEN + j], acc);
            if (j == 0) atomicAdd(&g_cnt[cur], (float)run);
            acc = 0.f; run = 0; cur = g;
        }
        acc += g_h[(size_t)(start + n) * HIDDEN + j];
        run++;
    }
    atomicAdd(&g_pool[cur * HIDDEN + j], acc);
    if (j == 0) atomicAdd(&g_cnt[cur], (float)run);
}

// ---------------- head ----------------
__global__ void k_head(const float* __restrict__ W1, const float* __restrict__ b1,
                       const float* __restrict__ W2, const float* __restrict__ b2,
                       float* __restrict__ out) {
    int gph = blockIdx.x;
    int j = threadIdx.x;  // 128
    __shared__ float sp[128], sg[128];
    float c = fmaxf(g_cnt[gph], 1.f);
    sp[j] = g_pool[gph * 128 + j] / c;
    __syncthreads();
    float v = b1[j];
#pragma unroll 8
    for (int k = 0; k < 128; k++) v += sp[k] * W1[k * 128 + j];
    sg[j] = fmaxf(v, 0.f);
    __syncthreads();
    if (j < 3) {
        float o = b2[j];
        for (int k = 0; k < 128; k++) o += sg[k] * W2[k * 3 + j];
        out[gph * 3 + j] = o;
    }
}

// ---------------- launch ----------------
extern "C" void kernel_launch(void* const* d_in, const int* in_sizes, int n_in,
                              void* d_out, int out_size) {
    const float* x   = (const float*)d_in[0];
    const int*   ei  = (const int*)d_in[1];
    const float* ea  = (const float*)d_in[2];
    const int*   bat = (const int*)d_in[3];
    const float* Wf1 = (const float*)d_in[4];
    const float* bf1 = (const float*)d_in[5];
    const float* Ws1 = (const float*)d_in[6];
    const float* bs1 = (const float*)d_in[7];
    const float* Wp  = (const float*)d_in[8];
    const float* bp  = (const float*)d_in[9];
    const float* Wf2 = (const float*)d_in[10];
    const float* bf2 = (const float*)d_in[11];
    const float* Ws2 = (const float*)d_in[12];
    const float* bs2 = (const float*)d_in[13];
    const float* Wf3 = (const float*)d_in[14];
    const float* bf3 = (const float*)d_in[15];
    const float* Ws3 = (const float*)d_in[16];
    const float* bs3 = (const float*)d_in[17];
    const float* W1  = (const float*)d_in[18];
    const float* b1  = (const float*)d_in[19];
    const float* W2  = (const float*)d_in[20];
    const float* b2  = (const float*)d_in[21];
    float* out = (float*)d_out;

    dim3 gemm_grid(4, (N_NODES + 127) / 128);
    int edge_grid = N_EDGES / (8 * ETILE);   // 25000, exact

    // sort edges by dst (count sort)
    k_zero_cnt<<<(N_NODES + 1023) / 1024, 1024>>>();
    k_hist<<<2048, 256>>>(ei);
    k_scan<<<1, SCAN_T>>>();
    k_scatter<<<2048, 256>>>(ei);

    // conv1 (channels=3)
    k_zero_agg1<<<(N_NODES * 3 + 255) / 256, 256>>>();
    k_conv1<<<4096, 256>>>(x, ei, ea, Wf1, bf1, Ws1, bs1);
    k_project<<<N_NODES, 128>>>(x, Wp, bp);

    // conv2
    k_pack<<<256, 256>>>(Wf2, Ws2);
    k_gemm<<<gemm_grid, 256>>>();
    k_edge<<<edge_grid, 256>>>(ea, Wf2, Ws2, bf2, bs2);
    k_relu<<<4096, 256>>>();

    // conv3
    k_pack<<<256, 256>>>(Wf3, Ws3);
    k_gemm<<<gemm_grid, 256>>>();
    k_edge<<<edge_grid, 256>>>(ea, Wf3, Ws3, bf3, bs3);
    k_relu<<<4096, 256>>>();

    // pool + head
    k_zero_pool<<<(N_GRAPHS * HIDDEN + 255) / 256, 256>>>();
    k_pool<<<(N_NODES + POOL_NODES - 1) / POOL_NODES, 128>>>(bat);
    k_head<<<N_GRAPHS, 128>>>(W1, b1, W2, b2, out);
}

// round 16
// speedup vs baseline: 1.2800x; 1.0006x over previous
#include <cuda_runtime.h>
#include <cuda_fp16.h>
#include <math.h>

#define N_NODES 100000
#define N_EDGES 1600000
#define HIDDEN  128
#define N_GRAPHS 64
#define ETILE   8

// ---------------- device scratch (static allocs only) ----------------
__device__ float  g_h   [N_NODES * HIDDEN];
__device__ __half g_P   [N_NODES * 512];       // 102.4 MB -> L2-resident
__device__ float  g_agg1[N_NODES * 3];
__device__ float  g_Wcat[128 * 512];
__device__ float  g_pool[N_GRAPHS * HIDDEN];
__device__ float  g_cnt [N_GRAPHS];
// sort scratch
__device__ int g_cntN [N_NODES];
__device__ int g_off2 [N_NODES];
__device__ int g_esrc [N_EDGES];
__device__ int g_edst [N_EDGES];
__device__ int g_eperm[N_EDGES];

// fast gates: __expf/__logf are MUFU-based; error ~2ulp, fine at 1e-3 tol
__device__ __forceinline__ float sigmoidf_(float x) {
    return __fdividef(1.f, 1.f + __expf(-x));
}
__device__ __forceinline__ float softplusf_(float x) {
    return fmaxf(x, 0.f) + __logf(1.f + __expf(-fabsf(x)));
}

// ---------------- packed f32x2 helpers (FFMA2) ----------------
typedef unsigned long long ull;
__device__ __forceinline__ ull pk2(float lo, float hi) {
    ull r; asm("mov.b64 %0, {%1, %2};" : "=l"(r) : "f"(lo), "f"(hi)); return r;
}
__device__ __forceinline__ ull fma2(ull a, ull b, ull c) {
    ull d; asm("fma.rn.f32x2 %0, %1, %2, %3;" : "=l"(d) : "l"(a), "l"(b), "l"(c)); return d;
}
__device__ __forceinline__ float2 upk(ull v) {
    float2 r; asm("mov.b64 {%0, %1}, %2;" : "=f"(r.x), "=f"(r.y) : "l"(v)); return r;
}

// ---------------- sort: count-sort edges by dst ----------------
__global__ void k_zero_cnt() {
    int i = blockIdx.x * blockDim.x + threadIdx.x;
    if (i < N_NODES) g_cntN[i] = 0;
}
__global__ void k_hist(const int* __restrict__ ei) {
    for (int e = blockIdx.x * blockDim.x + threadIdx.x; e < N_EDGES;
         e += gridDim.x * blockDim.x)
        atomicAdd(&g_cntN[ei[N_EDGES + e]], 1);
}
#define SCAN_T 1024
#define SCAN_C 98
__global__ void k_scan() {
    __shared__ int ssum[SCAN_T];
    int t = threadIdx.x;
    int base = t * SCAN_C;
    int lim = (base < N_NODES) ? min(SCAN_C, N_NODES - base) : 0;
    int s = 0;
    for (int i = 0; i < lim; i++) s += g_cntN[base + i];
    ssum[t] = s;
    __syncthreads();
    for (int d = 1; d < SCAN_T; d <<= 1) {
        int w = (t >= d) ? ssum[t - d] : 0;
        __syncthreads();
        ssum[t] += w;
        __syncthreads();
    }
    int run = ssum[t] - s;
    for (int i = 0; i < lim; i++) {
        int c = g_cntN[base + i];
        g_off2[base + i] = run;
        run += c;
    }
}
__global__ void k_scatter(const int* __restrict__ ei) {
    for (int e = blockIdx.x * blockDim.x + threadIdx.x; e < N_EDGES;
         e += gridDim.x * blockDim.x) {
        int dst = ei[N_EDGES + e];
        int pos = atomicAdd(&g_off2[dst], 1);
        g_esrc[pos]  = ei[e];
        g_edst[pos]  = dst;
        g_eperm[pos] = e;
    }
}

// ---------------- zero-init kernels ----------------
__global__ void k_zero_agg1() {
    int i = blockIdx.x * blockDim.x + threadIdx.x;
    if (i < N_NODES * 3) g_agg1[i] = 0.f;
}
__global__ void k_zero_pool() {
    int i = blockIdx.x * blockDim.x + threadIdx.x;
    if (i < N_GRAPHS * HIDDEN) g_pool[i] = 0.f;
    if (i < N_GRAPHS) g_cnt[i] = 0.f;
}

// ---------------- conv1: channels=3, direct per-edge ----------------
__global__ void k_conv1(const float* __restrict__ x, const int* __restrict__ ei,
                        const float* __restrict__ ea,
                        const float* __restrict__ Wf, const float* __restrict__ bf,
                        const float* __restrict__ Ws, const float* __restrict__ bs) {
    __shared__ float sWf[38 * 3], sWs[38 * 3], sbf[3], sbs[3];
    int tid = threadIdx.x;
    if (tid < 114) { sWf[tid] = Wf[tid]; sWs[tid] = Ws[tid]; }
    if (tid < 3)   { sbf[tid] = bf[tid]; sbs[tid] = bs[tid]; }
    __syncthreads();

    for (int e = blockIdx.x * blockDim.x + tid; e < N_EDGES; e += gridDim.x * blockDim.x) {
        int src = ei[e];
        int dst = ei[N_EDGES + e];
        float f[3], s[3];
#pragma unroll
        for (int c = 0; c < 3; c++) { f[c] = sbf[c]; s[c] = sbs[c]; }
#pragma unroll
        for (int i = 0; i < 3; i++) {
            float xv = x[dst * 3 + i];
#pragma unroll
            for (int c = 0; c < 3; c++) { f[c] += xv * sWf[i * 3 + c]; s[c] += xv * sWs[i * 3 + c]; }
        }
#pragma unroll
        for (int i = 0; i < 3; i++) {
            float xv = x[src * 3 + i];
#pragma unroll
            for (int c = 0; c < 3; c++) { f[c] += xv * sWf[(3 + i) * 3 + c]; s[c] += xv * sWs[(3 + i) * 3 + c]; }
        }
        const float4* ep = (const float4*)(ea + (size_t)e * 32);
#pragma unroll
        for (int q = 0; q < 8; q++) {
            float4 ev = ep[q];
            float evv[4] = {ev.x, ev.y, ev.z, ev.w};
#pragma unroll
            for (int j = 0; j < 4; j++) {
                int i = 6 + q * 4 + j;
#pragma unroll
                for (int c = 0; c < 3; c++) { f[c] += evv[j] * sWf[i * 3 + c]; s[c] += evv[j] * sWs[i * 3 + c]; }
            }
        }
#pragma unroll
        for (int c = 0; c < 3; c++) {
            float m = sigmoidf_(f[c]) * softplusf_(s[c]);
            atomicAdd(&g_agg1[dst * 3 + c], m);
        }
    }
}

// ---------------- project: h = relu((x + agg1) @ Wp + bp) ----------------
__global__ void k_project(const float* __restrict__ x, const float* __restrict__ Wp,
                          const float* __restrict__ bp) {
    int node = blockIdx.x;
    int j = threadIdx.x;  // 128
    __shared__ float xa[3];
    if (j < 3) xa[j] = x[node * 3 + j] + g_agg1[node * 3 + j];
    __syncthreads();
    float v = bp[j] + xa[0] * Wp[j] + xa[1] * Wp[128 + j] + xa[2] * Wp[256 + j];
    g_h[(size_t)node * HIDDEN + j] = fmaxf(v, 0.f);
}

// ---------------- pack Wcat[128,512] ----------------
__global__ void k_pack(const float* __restrict__ Wf, const float* __restrict__ Ws) {
    int idx = blockIdx.x * blockDim.x + threadIdx.x;
    if (idx >= 128 * 512) return;
    int k = idx >> 9, j = idx & 511;
    float v;
    if      (j < 128) v = Wf[k * 128 + j];
    else if (j < 256) v = Ws[k * 128 + (j - 128)];
    else if (j < 384) v = Wf[(k + 128) * 128 + (j - 256)];
    else              v = Ws[(k + 128) * 128 + (j - 384)];
    g_Wcat[idx] = v;
}

// ---------------- node GEMM: P[M,512] = h[M,128] @ Wcat[128,512] (fp16 out) ---
__global__ void k_gemm() {
    const int M = N_NODES;
    __shared__ float2 As2[8][128];
    __shared__ float  Bs[8][128];
    int tid = threadIdx.x;
    int tx = tid & 15, ty = tid >> 4;
    int bx = blockIdx.x;
    int rowBase = blockIdx.y * 128;

    ull acc2[8][4];
#pragma unroll
    for (int i = 0; i < 8; i++)
#pragma unroll
        for (int j = 0; j < 4; j++) acc2[i][j] = 0ull;

    int arow_l = tid >> 1;
    int arow   = rowBase + arow_l;
    int acol4  = (tid & 1) * 4;
    int brow   = tid >> 5;
    int bcol4  = (tid & 31) * 4;

    for (int k0 = 0; k0 < 128; k0 += 8) {
        float4 a = (arow < M) ? *(const float4*)&g_h[(size_t)arow * 128 + k0 + acol4]
                              : make_float4(0.f, 0.f, 0.f, 0.f);
        As2[acol4 + 0][arow_l] = make_float2(a.x, a.x);
        As2[acol4 + 1][arow_l] = make_float2(a.y, a.y);
        As2[acol4 + 2][arow_l] = make_float2(a.z, a.z);
        As2[acol4 + 3][arow_l] = make_float2(a.w, a.w);
        *(float4*)&Bs[brow][bcol4] =
            *(const float4*)&g_Wcat[(k0 + brow) * 512 + bx * 128 + bcol4];
        __syncthreads();
#pragma unroll
        for (int k = 0; k < 8; k++) {
            ull a2[8];
#pragma unroll
            for (int i = 0; i < 8; i++)
                a2[i] = *(const ull*)&As2[k][ty * 8 + i];
            ulonglong2 b0 = *(const ulonglong2*)&Bs[k][tx * 8];
            ulonglong2 b1 = *(const ulonglong2*)&Bs[k][tx * 8 + 4];
#pragma unroll
            for (int i = 0; i < 8; i++) {
                acc2[i][0] = fma2(a2[i], b0.x, acc2[i][0]);
                acc2[i][1] = fma2(a2[i], b0.y, acc2[i][1]);
                acc2[i][2] = fma2(a2[i], b1.x, acc2[i][2]);
                acc2[i][3] = fma2(a2[i], b1.y, acc2[i][3]);
            }
        }
        __syncthreads();
    }
#pragma unroll
    for (int i = 0; i < 8; i++) {
        int row = rowBase + ty * 8 + i;
        if (row < M) {
            float2 v0 = upk(acc2[i][0]), v1 = upk(acc2[i][1]);
            float2 v2 = upk(acc2[i][2]), v3 = upk(acc2[i][3]);
            __half2 h0 = __float22half2_rn(v0);
            __half2 h1 = __float22half2_rn(v1);
            __half2 h2 = __float22half2_rn(v2);
            __half2 h3 = __float22half2_rn(v3);
            uint4 pk;
            pk.x = *(unsigned*)&h0; pk.y = *(unsigned*)&h1;
            pk.z = *(unsigned*)&h2; pk.w = *(unsigned*)&h3;
            *(uint4*)&g_P[(size_t)row * 512 + bx * 128 + tx * 8] = pk;
        }
    }
}

// ---------------- edge kernel: dst-sorted, fp16 P gather, FFMA2 ----------------
__global__ void __launch_bounds__(256, 2)
k_edge(const float* __restrict__ ea,
       const float* __restrict__ Wf, const float* __restrict__ Ws,
       const float* __restrict__ bf, const float* __restrict__ bs) {
    __shared__ float sWf[32 * 128];
    __shared__ float sWs[32 * 128];
    __shared__ ull   se2[8][ETILE * 32];

    int tid = threadIdx.x;  // 256
    for (int i = tid; i < 32 * 128 / 4; i += 256) {
        ((float4*)sWf)[i] = ((const float4*)(Wf + 256 * 128))[i];
        ((float4*)sWs)[i] = ((const float4*)(Ws + 256 * 128))[i];
    }
    __syncthreads();

    int warp = tid >> 5, lane = tid & 31;
    float4 bfv = *(const float4*)&bf[lane * 4];
    float4 bsv = *(const float4*)&bs[lane * 4];

    int e0 = blockIdx.x * (8 * ETILE) + warp * ETILE;

    int vsrc = 0, vdst = 0, vprm = 0;
    if (lane < ETILE) {
        vsrc = g_esrc[e0 + lane];
        vdst = g_edst[e0 + lane];
        vprm = g_eperm[e0 + lane];
    }

#pragma unroll
    for (int t = 0; t < ETILE; t++) {
        int prm = __shfl_sync(0xffffffffu, vprm, t);
        float ev = __ldg(&ea[(size_t)prm * 32 + lane]);
        se2[warp][t * 32 + lane] = pk2(ev, ev);
    }

    ull fA[ETILE][2], sA[ETILE][2];
    int dsts[ETILE];
#pragma unroll
    for (int t = 0; t < ETILE; t++) {
        int src = __shfl_sync(0xffffffffu, vsrc, t);
        int dst = __shfl_sync(0xffffffffu, vdst, t);
        dsts[t] = dst;
        // fp16 P rows: [f_dst 128 | s_dst 128 | f_src 128 | s_src 128] halves
        const uint2* Pd = (const uint2*)&g_P[(size_t)dst * 512];
        const uint2* Ps = (const uint2*)&g_P[(size_t)src * 512 + 256];
        uint2 fd2 = __ldg(&Pd[lane]);      // 4 halves
        uint2 sd2 = __ldg(&Pd[32 + lane]);
        uint2 fs2 = __ldg(&Ps[lane]);
        uint2 ss2 = __ldg(&Ps[32 + lane]);
        float2 fd01 = __half22float2(*(const __half2*)&fd2.x);
        float2 fd23 = __half22float2(*(const __half2*)&fd2.y);
        float2 sd01 = __half22float2(*(const __half2*)&sd2.x);
        float2 sd23 = __half22float2(*(const __half2*)&sd2.y);
        float2 fs01 = __half22float2(*(const __half2*)&fs2.x);
        float2 fs23 = __half22float2(*(const __half2*)&fs2.y);
        float2 ss01 = __half22float2(*(const __half2*)&ss2.x);
        float2 ss23 = __half22float2(*(const __half2*)&ss2.y);
        fA[t][0] = pk2(fd01.x + fs01.x + bfv.x, fd01.y + fs01.y + bfv.y);
        fA[t][1] = pk2(fd23.x + fs23.x + bfv.z, fd23.y + fs23.y + bfv.w);
        sA[t][0] = pk2(sd01.x + ss01.x + bsv.x, sd01.y + ss01.y + bsv.y);
        sA[t][1] = pk2(sd23.x + ss23.x + bsv.z, sd23.y + ss23.y + bsv.w);
    }
    __syncwarp();

#pragma unroll 8
    for (int k = 0; k < 32; k++) {
        ulonglong2 wf = *(const ulonglong2*)&sWf[k * 128 + lane * 4];
        ulonglong2 ws = *(const ulonglong2*)&sWs[k * 128 + lane * 4];
#pragma unroll
        for (int t = 0; t < ETILE; t++) {
            ull e2 = se2[warp][t * 32 + k];
            fA[t][0] = fma2(e2, wf.x, fA[t][0]);
            fA[t][1] = fma2(e2, wf.y, fA[t][1]);
            sA[t][0] = fma2(e2, ws.x, sA[t][0]);
            sA[t][1] = fma2(e2, ws.y, sA[t][1]);
        }
    }

    // run-accumulated epilogue: one atomic per dst-run
    float4 acc = make_float4(0.f, 0.f, 0.f, 0.f);
    int cur = dsts[0];
#pragma unroll
    for (int t = 0; t < ETILE; t++) {
        float2 f0 = upk(fA[t][0]), f1 = upk(fA[t][1]);
        float2 s0 = upk(sA[t][0]), s1 = upk(sA[t][1]);
        float4 m;
        m.x = sigmoidf_(f0.x) * softplusf_(s0.x);
        m.y = sigmoidf_(f0.y) * softplusf_(s0.y);
        m.z = sigmoidf_(f1.x) * softplusf_(s1.x);
        m.w = sigmoidf_(f1.y) * softplusf_(s1.y);
        if (dsts[t] != cur) {
            atomicAdd((float4*)&g_h[(size_t)cur * 128 + lane * 4], acc);
            acc = make_float4(0.f, 0.f, 0.f, 0.f);
            cur = dsts[t];
        }
        acc.x += m.x; acc.y += m.y; acc.z += m.z; acc.w += m.w;
    }
    atomicAdd((float4*)&g_h[(size_t)cur * 128 + lane * 4], acc);
}

// ---------------- relu in place on g_h ----------------
__global__ void k_relu() {
    int n4 = N_NODES * HIDDEN / 4;
    for (int i = blockIdx.x * blockDim.x + threadIdx.x; i < n4; i += gridDim.x * blockDim.x) {
        float4 v = ((const float4*)g_h)[i];
        v.x = fmaxf(v.x, 0.f); v.y = fmaxf(v.y, 0.f);
        v.z = fmaxf(v.z, 0.f); v.w = fmaxf(v.w, 0.f);
        ((float4*)g_h)[i] = v;
    }
}

// ---------------- mean pool (batch sorted) ----------------
#define POOL_NODES 64
__global__ void k_pool(const int* __restrict__ batch) {
    __shared__ int sb[POOL_NODES];
    int j = threadIdx.x;  // 128
    int start = blockIdx.x * POOL_NODES;
    int cnt_here = min(POOL_NODES, N_NODES - start);
    for (int i = j; i < cnt_here; i += blockDim.x) sb[i] = batch[start + i];
    __syncthreads();
    float acc = 0.f;
    int cur = sb[0];
    int run = 0;
    for (int n = 0; n < cnt_here; n++) {
        int g = sb[n];
        if (g != cur) {
            atomicAdd(&g_pool[cur * HIDDEN + j], acc);
            if (j == 0) atomicAdd(&g_cnt[cur], (float)run);
            acc = 0.f; run = 0; cur = g;
        }
        acc += g_h[(size_t)(start + n) * HIDDEN + j];
        run++;
    }
    atomicAdd(&g_pool[cur * HIDDEN + j], acc);
    if (j == 0) atomicAdd(&g_cnt[cur], (float)run);
}

// ---------------- head ----------------
__global__ void k_head(const float* __restrict__ W1, const float* __restrict__ b1,
                       const float* __restrict__ W2, const float* __restrict__ b2,
                       float* __restrict__ out) {
    int gph = blockIdx.x;
    int j = threadIdx.x;  // 128
    __shared__ float sp[128], sg[128];
    float c = fmaxf(g_cnt[gph], 1.f);
    sp[j] = g_pool[gph * 128 + j] / c;
    __syncthreads();
    float v = b1[j];
#pragma unroll 8
    for (int k = 0; k < 128; k++) v += sp[k] * W1[k * 128 + j];
    sg[j] = fmaxf(v, 0.f);
    __syncthreads();
    if (j < 3) {
        float o = b2[j];
        for (int k = 0; k < 128; k++) o += sg[k] * W2[k * 3 + j];
        out[gph * 3 + j] = o;
    }
}

// ---------------- launch ----------------
extern "C" void kernel_launch(void* const* d_in, const int* in_sizes, int n_in,
                              void* d_out, int out_size) {
    const float* x   = (const float*)d_in[0];
    const int*   ei  = (const int*)d_in[1];
    const float* ea  = (const float*)d_in[2];
    const int*   bat = (const int*)d_in[3];
    const float* Wf1 = (const float*)d_in[4];
    const float* bf1 = (const float*)d_in[5];
    const float* Ws1 = (const float*)d_in[6];
    const float* bs1 = (const float*)d_in[7];
    const float* Wp  = (const float*)d_in[8];
    const float* bp  = (const float*)d_in[9];
    const float* Wf2 = (const float*)d_in[10];
    const float* bf2 = (const float*)d_in[11];
    const float* Ws2 = (const float*)d_in[12];
    const float* bs2 = (const float*)d_in[13];
    const float* Wf3 = (const float*)d_in[14];
    const float* bf3 = (const float*)d_in[15];
    const float* Ws3 = (const float*)d_in[16];
    const float* bs3 = (const float*)d_in[17];
    const float* W1  = (const float*)d_in[18];
    const float* b1  = (const float*)d_in[19];
    const float* W2  = (const float*)d_in[20];
    const float* b2  = (const float*)d_in[21];
    float* out = (float*)d_out;

    dim3 gemm_grid(4, (N_NODES + 127) / 128);
    int edge_grid = N_EDGES / (8 * ETILE);   // 25000, exact

    // sort edges by dst (count sort)
    k_zero_cnt<<<(N_NODES + 1023) / 1024, 1024>>>();
    k_hist<<<2048, 256>>>(ei);
    k_scan<<<1, SCAN_T>>>();
    k_scatter<<<2048, 256>>>(ei);

    // conv1 (channels=3)
    k_zero_agg1<<<(N_NODES * 3 + 255) / 256, 256>>>();
    k_conv1<<<4096, 256>>>(x, ei, ea, Wf1, bf1, Ws1, bs1);
    k_project<<<N_NODES, 128>>>(x, Wp, bp);

    // conv2
    k_pack<<<256, 256>>>(Wf2, Ws2);
    k_gemm<<<gemm_grid, 256>>>();
    k_edge<<<edge_grid, 256>>>(ea, Wf2, Ws2, bf2, bs2);
    k_relu<<<4096, 256>>>();

    // conv3
    k_pack<<<256, 256>>>(Wf3, Ws3);
    k_gemm<<<gemm_grid, 256>>>();
    k_edge<<<edge_grid, 256>>>(ea, Wf3, Ws3, bf3, bs3);
    k_relu<<<4096, 256>>>();

    // pool + head
    k_zero_pool<<<(N_GRAPHS * HIDDEN + 255) / 256, 256>>>();
    k_pool<<<(N_NODES + POOL_NODES - 1) / POOL_NODES, 128>>>(bat);
    k_head<<<N_GRAPHS, 128>>>(W1, b1, W2, b2, out);
}